// round 7
// baseline (speedup 1.0000x reference)
#include <cuda_runtime.h>
#include <cuda_bf16.h>
#include <cstdint>
#include <cstddef>

typedef __nv_bfloat16 bf16;
typedef unsigned int u32;

#define NN 4096
#define DD 128
#define NB 2
#define RHO 5
#define NJ 5
#define KC 64
#define STAGE_B 32768          // A(hi+lo) 16KB + B(hi+lo) 16KB
#define SMEM_TOTAL (2 * STAGE_B)

// ---------------- device scratch ----------------
__device__ bf16 g_U_hi[(size_t)NB * NN * NN];
__device__ bf16 g_U_lo[(size_t)NB * NN * NN];
__device__ bf16 g_x_hi[(size_t)NB * NN * DD];
__device__ bf16 g_x_lo[(size_t)NB * NN * DD];
__device__ bf16 g_Z_hi[(size_t)NB * NN * DD];
__device__ bf16 g_Z_lo[(size_t)NB * NN * DD];
__device__ float g_xt[(size_t)NB * NN * DD];
__device__ float g_p0[(size_t)NB * NN * DD];
__device__ float g_p1[(size_t)NB * NN * DD];
__device__ bf16 g_F_hi[(size_t)NB * NN * 6 * DD];
__device__ bf16 g_F_lo[(size_t)NB * NN * 6 * DD];
__device__ bf16 g_Wc_hi[6 * DD * DD];   // [768 k][128 d]
__device__ bf16 g_Wc_lo[6 * DD * DD];
__device__ float g_partial[NB * 32 * DD];
__device__ float g_acoef[NB * 8];
__device__ float g_bcoef[NB * 8];
__device__ float g_scale[NB * 8];
__device__ float g_cvec[DD];

// ---------------- helpers ----------------
__device__ __forceinline__ u32 smem_u32(const void* p) {
    u32 a;
    asm("{ .reg .u64 t; cvta.to.shared.u64 t, %1; cvt.u32.u64 %0, t; }" : "=r"(a) : "l"(p));
    return a;
}
__device__ __forceinline__ void split2(float v, bf16& h, bf16& l) {
    h = __float2bfloat16_rn(v);
    l = __float2bfloat16_rn(v - __bfloat162float(h));
}
__device__ __forceinline__ u32 packb(bf16 a, bf16 b) {
    return (u32)__bfloat16_as_ushort(a) | ((u32)__bfloat16_as_ushort(b) << 16);
}
__device__ __forceinline__ void ldsm4(u32 a, u32* r) {
    asm volatile("ldmatrix.sync.aligned.m8n8.x4.shared.b16 {%0,%1,%2,%3}, [%4];"
                 : "=r"(r[0]), "=r"(r[1]), "=r"(r[2]), "=r"(r[3]) : "r"(a));
}
__device__ __forceinline__ void ldsm4t(u32 a, u32* r) {
    asm volatile("ldmatrix.sync.aligned.m8n8.x4.trans.shared.b16 {%0,%1,%2,%3}, [%4];"
                 : "=r"(r[0]), "=r"(r[1]), "=r"(r[2]), "=r"(r[3]) : "r"(a));
}
__device__ __forceinline__ void mma16816(float* c, const u32* a, const u32* b) {
    asm volatile(
        "mma.sync.aligned.m16n8k16.row.col.f32.bf16.bf16.f32 "
        "{%0,%1,%2,%3}, {%4,%5,%6,%7}, {%8,%9}, {%0,%1,%2,%3};"
        : "+f"(c[0]), "+f"(c[1]), "+f"(c[2]), "+f"(c[3])
        : "r"(a[0]), "r"(a[1]), "r"(a[2]), "r"(a[3]), "r"(b[0]), "r"(b[1]));
}

// ---------------- elementwise fp32 -> bf16 hi/lo ----------------
__global__ void convert_split_kernel(const float* __restrict__ src, bf16* __restrict__ oh,
                                     bf16* __restrict__ ol) {
    size_t idx = (size_t)blockIdx.x * blockDim.x + threadIdx.x;
    float4 v = ((const float4*)src)[idx];
    bf16 h0, l0, h1, l1, h2, l2, h3, l3;
    split2(v.x, h0, l0); split2(v.y, h1, l1);
    split2(v.z, h2, l2); split2(v.w, h3, l3);
    ((u32*)oh)[idx * 2] = packb(h0, h1);
    ((u32*)oh)[idx * 2 + 1] = packb(h2, h3);
    ((u32*)ol)[idx * 2] = packb(l0, l1);
    ((u32*)ol)[idx * 2 + 1] = packb(l2, l3);
}

// ---------------- split-K combine kernels (deterministic, no atomics) ----------------
__global__ void combine_kernel(const float* __restrict__ p0, const float* __restrict__ p1,
                               float* __restrict__ dst) {
    size_t i = (size_t)blockIdx.x * blockDim.x + threadIdx.x;
    float4 a = ((const float4*)p0)[i], b = ((const float4*)p1)[i];
    ((float4*)dst)[i] = make_float4(a.x + b.x, a.y + b.y, a.z + b.z, a.w + b.w);
}
__global__ void combine_bias_kernel(const float* __restrict__ p0, const float* __restrict__ p1,
                                    const float* __restrict__ bias, float* __restrict__ dst) {
    size_t i = (size_t)blockIdx.x * blockDim.x + threadIdx.x;
    int col = ((int)(i & 31)) * 4;
    float4 a = ((const float4*)p0)[i], b = ((const float4*)p1)[i];
    ((float4*)dst)[i] = make_float4(a.x + b.x + bias[col], a.y + b.y + bias[col + 1],
                                    a.z + b.z + bias[col + 2], a.w + b.w + bias[col + 3]);
}

// ---------------- coefficient path (validated R1/R4) ----------------
__global__ void partial_kernel(const float* __restrict__ eigvs) {
    int b = blockIdx.x >> 5, chunk = blockIdx.x & 31, d = threadIdx.x;
    const float* p = eigvs + ((size_t)b * NN + (size_t)chunk * 128) * DD + d;
    float s = 0.f;
#pragma unroll 8
    for (int r = 0; r < 128; r++) s += p[(size_t)r * DD];
    g_partial[(b * 32 + chunk) * DD + d] = s;
}

__global__ void coeff_kernel(const float* __restrict__ Wa, const float* __restrict__ ba,
                             const float* __restrict__ Wb, const float* __restrict__ bb,
                             const float* __restrict__ Ws, const float* __restrict__ bs) {
    __shared__ float mean[DD];
    int b = blockIdx.x, d = threadIdx.x;
    float s = 0.f;
    for (int c = 0; c < 32; c++) s += g_partial[(b * 32 + c) * DD + d];
    mean[d] = s * (1.0f / NN);
    __syncthreads();
    if (d < RHO) {
        float a = 0.f, bv = 0.f, sv = 0.f;
        for (int e = 0; e < DD; e++) {
            float m = mean[e];
            a += m * Wa[e * RHO + d];
            bv += m * Wb[e * RHO + d];
            sv += m * Ws[e * NJ + d];
        }
        g_acoef[b * 8 + d] = a + ba[d];
        g_bcoef[b * 8 + d] = bv + bb[d];
        sv += bs[d];
        g_scale[b * 8 + d] = 5.0f / (1.0f + expf(-sv));
    }
}

__global__ void weight_kernel(const float* __restrict__ WS_, const float* __restrict__ WM,
                              const float* __restrict__ Ww, const float* __restrict__ bS,
                              const float* __restrict__ bM, const float* __restrict__ bw) {
    int blk = blockIdx.x, d = threadIdx.x;
    if (blk < 6 * DD) {
        int s = blk >> 7, i = blk & 127;
        const float* wsrc = (s == 0) ? (WS_ + i * DD) : (WM + (size_t)(s - 1) * DD * DD + i * DD);
        float acc = 0.f;
        for (int e = 0; e < DD; e++) acc += wsrc[e] * Ww[e * DD + d];
        bf16 h, l; split2(acc, h, l);
        g_Wc_hi[(size_t)blk * DD + d] = h;
        g_Wc_lo[(size_t)blk * DD + d] = l;
    } else {
        float acc = bw[d];
        for (int e = 0; e < DD; e++) {
            float cb = bS[e];
            for (int j = 0; j < NJ; j++) cb += bM[j * DD + e];
            acc += cb * Ww[e * DD + d];
        }
        g_cvec[d] = acc;
    }
}

__global__ void fbuild_kernel(const float* __restrict__ eigvs) {
    int row0 = blockIdx.x * 16, d = threadIdx.x;
    for (int r = 0; r < 16; r++) {
        int row = row0 + r, b = row >> 12;
        const float* ac = g_acoef + b * 8;
        const float* bc = g_bcoef + b * 8;
        const float* sc = g_scale + b * 8;
        float e = eigvs[(size_t)row * DD + d];
        float xv = g_xt[(size_t)row * DD + d];
        float To = 1.f, Te = e, h = bc[0];
#pragma unroll
        for (int i = 1; i < RHO; i++) {
            To = 2.f * e * Te - To;
            Te = 2.f * e * To - Te;
            h += bc[i] * To;
        }
        size_t fb = (size_t)row * (6 * DD);
        bf16 hh, hl; split2(h * xv, hh, hl);
        g_F_hi[fb + d] = hh; g_F_lo[fb + d] = hl;
#pragma unroll
        for (int j = 0; j < NJ; j++) {
            float sx = sc[j] * e;
            float To2 = 1.f, Te2 = sx, g = ac[0] * Te2;
#pragma unroll
            for (int i = 1; i < RHO; i++) {
                To2 = 2.f * sx * Te2 - To2;
                Te2 = 2.f * sx * To2 - Te2;
                g += ac[i] * Te2;
            }
            bf16 gh, gl; split2(g * xv, gh, gl);
            g_F_hi[fb + (1 + j) * DD + d] = gh;
            g_F_lo[fb + (1 + j) * DD + d] = gl;
        }
    }
}

// ---------------- mma.sync GEMM, BM=64 x BN=64, 128 threads, 2 stages ----------------
// Stage layout (32KB): A_hi[0,8K) A_lo[8K,16K) B_hi[16K,24K) B_lo[24K,32K)
// Rows are 64 x 128B with per-row 16B-chunk swizzle (ch ^ (row&7)).
// Split-K: blockIdx.z = batch*nsplit + ks; CTA handles K rows [ks*K/nsplit, ...).
template <bool TRANSA>
__device__ __forceinline__ void loadA_async(u32 Abase, int k0, const bf16* Ah, const bf16* Al,
                                            int lda, int tid) {
#pragma unroll
    for (int half = 0; half < 2; half++) {
        const bf16* src = half ? Al : Ah;
        u32 ab = Abase + half * 8192;
#pragma unroll
        for (int i = 0; i < 4; i++) {
            int q = tid + i * 128;
            int row = q >> 3, ch = q & 7;
            const char* g;
            if (TRANSA) g = (const char*)(src + (size_t)(k0 + row) * lda) + ch * 16;
            else        g = (const char*)(src + (size_t)row * lda + k0) + ch * 16;
            u32 dst = ab + row * 128 + ((ch ^ (row & 7)) * 16);
            asm volatile("cp.async.cg.shared.global [%0], [%1], 16;" :: "r"(dst), "l"(g));
        }
    }
}

__device__ __forceinline__ void loadB_async(u32 Bbase, int k0, const bf16* Bh, const bf16* Bl,
                                            int ldb, int tid) {
#pragma unroll
    for (int half = 0; half < 2; half++) {
        const bf16* src = half ? Bl : Bh;
        u32 bb = Bbase + half * 8192;
#pragma unroll
        for (int i = 0; i < 4; i++) {
            int q = tid + i * 128;
            int kr = q >> 3, ch = q & 7;
            const char* g = (const char*)(src + (size_t)(k0 + kr) * ldb) + ch * 16;
            u32 dst = bb + kr * 128 + ((ch ^ (kr & 7)) * 16);
            asm volatile("cp.async.cg.shared.global [%0], [%1], 16;" :: "r"(dst), "l"(g));
        }
    }
}

// OUTMODE: 0 = fp32 partial (C0/C1 by ks), 2 = bf16 hi/lo split output
template <bool TRANSA, int OUTMODE>
__global__ void __launch_bounds__(128, 3)
mma_gemm(const bf16* __restrict__ Ah, const bf16* __restrict__ Al,
         const bf16* __restrict__ Bh, const bf16* __restrict__ Bl,
         float* __restrict__ C0, float* __restrict__ C1,
         bf16* __restrict__ Zh, bf16* __restrict__ Zl,
         int nsplit, int K, int lda, int ldb, size_t aB, size_t bB, size_t cB) {
    extern __shared__ char smem[];
    u32 sb = smem_u32(smem);
    int tid = threadIdx.x, lane = tid & 31, wid = tid >> 5;
    int wm = wid & 1, wn = wid >> 1;
    int bx = blockIdx.x, nh = blockIdx.y;
    int bz = blockIdx.z / nsplit, ks = blockIdx.z - bz * nsplit;
    const int Klocal = K / nsplit;
    const int kofs = ks * Klocal;

    Ah += bz * aB; Al += bz * aB;
    if (TRANSA) { Ah += (size_t)kofs * lda + (size_t)bx * 64; Al += (size_t)kofs * lda + (size_t)bx * 64; }
    else        { Ah += (size_t)bx * 64 * lda + kofs;         Al += (size_t)bx * 64 * lda + kofs; }
    Bh += bz * bB + (size_t)kofs * ldb + (size_t)nh * 64;
    Bl += bz * bB + (size_t)kofs * ldb + (size_t)nh * 64;

    float acc[2][4][4];
#pragma unroll
    for (int a = 0; a < 2; a++)
#pragma unroll
        for (int b = 0; b < 4; b++)
#pragma unroll
            for (int c = 0; c < 4; c++) acc[a][b][c] = 0.f;

    const int NCH = Klocal / KC;

#pragma unroll
    for (int s = 0; s < 2; s++) {
        u32 Abase = sb + s * STAGE_B;
        loadA_async<TRANSA>(Abase, s * KC, Ah, Al, lda, tid);
        loadB_async(Abase + 16384, s * KC, Bh, Bl, ldb, tid);
        asm volatile("cp.async.commit_group;" ::: "memory");
    }

    for (int c = 0; c < NCH; c++) {
        int st = c & 1;
        if (c + 1 < NCH) asm volatile("cp.async.wait_group 1;" ::: "memory");
        else             asm volatile("cp.async.wait_group 0;" ::: "memory");
        __syncthreads();

        u32 Ab = sb + st * STAGE_B;
        u32 Bb = Ab + 16384;
#pragma unroll
        for (int s = 0; s < 4; s++) {
            u32 ah[2][4], al[2][4], bh[2][4], bl[2][4];
#pragma unroll
            for (int mt = 0; mt < 2; mt++) {
                u32 off;
                if (TRANSA) {
                    int kr = 16 * s + (lane & 7) + ((lane >> 4) << 3);
                    int mch = wm * 4 + mt * 2 + ((lane >> 3) & 1);
                    off = kr * 128 + ((mch ^ (kr & 7)) << 4);
                    ldsm4t(Ab + off, ah[mt]);
                    ldsm4t(Ab + 8192 + off, al[mt]);
                } else {
                    int row = wm * 32 + mt * 16 + (lane & 15);
                    int ch = 2 * s + (lane >> 4);
                    off = row * 128 + ((ch ^ (row & 7)) << 4);
                    ldsm4(Ab + off, ah[mt]);
                    ldsm4(Ab + 8192 + off, al[mt]);
                }
            }
#pragma unroll
            for (int nt = 0; nt < 2; nt++) {
                int kr = 16 * s + (lane & 7) + ((lane >> 3) & 1) * 8;
                int nch = wn * 4 + nt * 2 + (lane >> 4);
                u32 off = kr * 128 + ((nch ^ (kr & 7)) << 4);
                ldsm4t(Bb + off, bh[nt]);
                ldsm4t(Bb + 8192 + off, bl[nt]);
            }
#pragma unroll
            for (int mt = 0; mt < 2; mt++)
#pragma unroll
                for (int nt = 0; nt < 2; nt++)
#pragma unroll
                    for (int oc = 0; oc < 2; oc++) {
                        float* cc = acc[mt][nt * 2 + oc];
                        mma16816(cc, ah[mt], &bh[nt][oc * 2]);
                        mma16816(cc, ah[mt], &bl[nt][oc * 2]);
                        mma16816(cc, al[mt], &bh[nt][oc * 2]);
                    }
        }
        __syncthreads();
        if (c + 2 < NCH) {
            u32 Abase = sb + st * STAGE_B;
            loadA_async<TRANSA>(Abase, (c + 2) * KC, Ah, Al, lda, tid);
            loadB_async(Abase + 16384, (c + 2) * KC, Bh, Bl, ldb, tid);
            asm volatile("cp.async.commit_group;" ::: "memory");
        }
    }

    // epilogue
    float* C = (ks == 0) ? C0 : C1;
#pragma unroll
    for (int mt = 0; mt < 2; mt++)
#pragma unroll
        for (int j = 0; j < 4; j++) {
            int mloc = bx * 64 + wm * 32 + mt * 16 + (lane >> 2);
            int col = nh * 64 + wn * 32 + j * 8 + (lane & 3) * 2;
#pragma unroll
            for (int rr = 0; rr < 2; rr++) {
                float v0 = acc[mt][j][rr * 2], v1 = acc[mt][j][rr * 2 + 1];
                size_t off = (size_t)(mloc + rr * 8) * 128 + col;
                if (OUTMODE == 2) {
                    bf16 h0, l0, h1, l1;
                    split2(v0, h0, l0); split2(v1, h1, l1);
                    *(u32*)(Zh + bz * cB + off) = packb(h0, h1);
                    *(u32*)(Zl + bz * cB + off) = packb(l0, l1);
                } else {
                    *(float2*)(C + bz * cB + off) = make_float2(v0, v1);
                }
            }
        }
}

// ---------------------------------------------------------------
extern "C" void kernel_launch(void* const* d_in, const int* in_sizes, int n_in,
                              void* d_out, int out_size) {
    const float* eigvs = (const float*)d_in[0];
    const float* x = (const float*)d_in[1];
    const float* U = (const float*)d_in[2];
    const float* Wa = (const float*)d_in[3];
    const float* ba = (const float*)d_in[4];
    const float* Wb = (const float*)d_in[5];
    const float* bb = (const float*)d_in[6];
    const float* Ws = (const float*)d_in[7];
    const float* bs = (const float*)d_in[8];
    const float* WS_ = (const float*)d_in[9];
    const float* bS = (const float*)d_in[10];
    const float* WM = (const float*)d_in[11];
    const float* bM = (const float*)d_in[12];
    const float* Ww = (const float*)d_in[13];
    const float* bw = (const float*)d_in[14];
    float* out = (float*)d_out;

    cudaFuncSetAttribute(mma_gemm<true, 0>, cudaFuncAttributeMaxDynamicSharedMemorySize, SMEM_TOTAL);
    cudaFuncSetAttribute(mma_gemm<false, 2>, cudaFuncAttributeMaxDynamicSharedMemorySize, SMEM_TOTAL);
    cudaFuncSetAttribute(mma_gemm<false, 0>, cudaFuncAttributeMaxDynamicSharedMemorySize, SMEM_TOTAL);

    bf16 *pUh, *pUl, *pxh, *pxl, *pZh, *pZl, *pFh, *pFl, *pWh, *pWl;
    float *pxt, *pcv, *pp0, *pp1;
    cudaGetSymbolAddress((void**)&pUh, g_U_hi);
    cudaGetSymbolAddress((void**)&pUl, g_U_lo);
    cudaGetSymbolAddress((void**)&pxh, g_x_hi);
    cudaGetSymbolAddress((void**)&pxl, g_x_lo);
    cudaGetSymbolAddress((void**)&pZh, g_Z_hi);
    cudaGetSymbolAddress((void**)&pZl, g_Z_lo);
    cudaGetSymbolAddress((void**)&pFh, g_F_hi);
    cudaGetSymbolAddress((void**)&pFl, g_F_lo);
    cudaGetSymbolAddress((void**)&pWh, g_Wc_hi);
    cudaGetSymbolAddress((void**)&pWl, g_Wc_lo);
    cudaGetSymbolAddress((void**)&pxt, g_xt);
    cudaGetSymbolAddress((void**)&pcv, g_cvec);
    cudaGetSymbolAddress((void**)&pp0, g_p0);
    cudaGetSymbolAddress((void**)&pp1, g_p1);

    const size_t sU = (size_t)NN * NN;
    const size_t sX = (size_t)NN * DD;

    convert_split_kernel<<<32768, 256>>>(U, pUh, pUl);
    convert_split_kernel<<<1024, 256>>>(x, pxh, pxl);
    partial_kernel<<<64, 128>>>(eigvs);

    // xt = U^T x : split-K=2, partials then combine
    mma_gemm<true, 0><<<dim3(64, 2, 4), 128, SMEM_TOTAL>>>(
        pUh, pUl, pxh, pxl, pp0, pp1, nullptr, nullptr,
        2, NN, NN, DD, sU, sX, sX);
    combine_kernel<<<1024, 256>>>(pp0, pp1, pxt);

    weight_kernel<<<769, 128>>>(WS_, WM, Ww, bS, bM, bw);
    coeff_kernel<<<2, 128>>>(Wa, ba, Wb, bb, Ws, bs);
    fbuild_kernel<<<512, 128>>>(eigvs);

    // Z = F @ Wc : flat M=8192, K=768; unsplit; output split bf16
    mma_gemm<false, 2><<<dim3(128, 2, 1), 128, SMEM_TOTAL>>>(
        pFh, pFl, pWh, pWl, nullptr, nullptr, pZh, pZl,
        1, 6 * DD, 6 * DD, DD, 0, 0, 0);

    // out = U @ Z + cvec : split-K=2, partials then combine with bias
    mma_gemm<false, 0><<<dim3(64, 2, 4), 128, SMEM_TOTAL>>>(
        pUh, pUl, pZh, pZl, pp0, pp1, nullptr, nullptr,
        2, NN, NN, DD, sU, sX, sX);
    combine_bias_kernel<<<1024, 256>>>(pp0, pp1, pcv, out);
}

// round 8
// speedup vs baseline: 1.0088x; 1.0088x over previous
#include <cuda_runtime.h>
#include <cuda_bf16.h>
#include <cstdint>
#include <cstddef>

typedef __nv_bfloat16 bf16;
typedef unsigned int u32;

#define NN 4096
#define DD 128
#define NB 2
#define RHO 5
#define NJ 5
#define KC 64
#define STAGE_B 32768          // A(hi+lo) 16KB + B(hi+lo) 16KB
#define SMEM_TOTAL (2 * STAGE_B)

// ---------------- device scratch ----------------
__device__ bf16 g_U_hi[(size_t)NB * NN * NN];
__device__ bf16 g_U_lo[(size_t)NB * NN * NN];
__device__ bf16 g_x_hi[(size_t)NB * NN * DD];
__device__ bf16 g_x_lo[(size_t)NB * NN * DD];
__device__ bf16 g_Z_hi[(size_t)NB * NN * DD];
__device__ bf16 g_Z_lo[(size_t)NB * NN * DD];
__device__ float g_p0[(size_t)NB * NN * DD];
__device__ float g_p1[(size_t)NB * NN * DD];
__device__ bf16 g_F_hi[(size_t)NB * NN * 6 * DD];
__device__ bf16 g_F_lo[(size_t)NB * NN * 6 * DD];
__device__ bf16 g_Wc_hi[6 * DD * DD];   // [768 k][128 d]
__device__ bf16 g_Wc_lo[6 * DD * DD];
__device__ float g_partial[NB * 32 * DD];
__device__ float g_acoef[NB * 8];
__device__ float g_bcoef[NB * 8];
__device__ float g_scale[NB * 8];
__device__ float g_cvec[DD];

// ---------------- helpers ----------------
__device__ __forceinline__ u32 smem_u32(const void* p) {
    u32 a;
    asm("{ .reg .u64 t; cvta.to.shared.u64 t, %1; cvt.u32.u64 %0, t; }" : "=r"(a) : "l"(p));
    return a;
}
__device__ __forceinline__ void split2(float v, bf16& h, bf16& l) {
    h = __float2bfloat16_rn(v);
    l = __float2bfloat16_rn(v - __bfloat162float(h));
}
__device__ __forceinline__ u32 packb(bf16 a, bf16 b) {
    return (u32)__bfloat16_as_ushort(a) | ((u32)__bfloat16_as_ushort(b) << 16);
}
__device__ __forceinline__ void ldsm4(u32 a, u32* r) {
    asm volatile("ldmatrix.sync.aligned.m8n8.x4.shared.b16 {%0,%1,%2,%3}, [%4];"
                 : "=r"(r[0]), "=r"(r[1]), "=r"(r[2]), "=r"(r[3]) : "r"(a));
}
__device__ __forceinline__ void ldsm4t(u32 a, u32* r) {
    asm volatile("ldmatrix.sync.aligned.m8n8.x4.trans.shared.b16 {%0,%1,%2,%3}, [%4];"
                 : "=r"(r[0]), "=r"(r[1]), "=r"(r[2]), "=r"(r[3]) : "r"(a));
}
__device__ __forceinline__ void mma16816(float* c, const u32* a, const u32* b) {
    asm volatile(
        "mma.sync.aligned.m16n8k16.row.col.f32.bf16.bf16.f32 "
        "{%0,%1,%2,%3}, {%4,%5,%6,%7}, {%8,%9}, {%0,%1,%2,%3};"
        : "+f"(c[0]), "+f"(c[1]), "+f"(c[2]), "+f"(c[3])
        : "r"(a[0]), "r"(a[1]), "r"(a[2]), "r"(a[3]), "r"(b[0]), "r"(b[1]));
}

// ---------------- elementwise fp32 -> bf16 hi/lo ----------------
__global__ void convert_split_kernel(const float* __restrict__ src, bf16* __restrict__ oh,
                                     bf16* __restrict__ ol) {
    size_t idx = (size_t)blockIdx.x * blockDim.x + threadIdx.x;
    float4 v = ((const float4*)src)[idx];
    bf16 h0, l0, h1, l1, h2, l2, h3, l3;
    split2(v.x, h0, l0); split2(v.y, h1, l1);
    split2(v.z, h2, l2); split2(v.w, h3, l3);
    ((u32*)oh)[idx * 2] = packb(h0, h1);
    ((u32*)oh)[idx * 2 + 1] = packb(h2, h3);
    ((u32*)ol)[idx * 2] = packb(l0, l1);
    ((u32*)ol)[idx * 2 + 1] = packb(l2, l3);
}

// ---------------- split-K bias combine (deterministic) ----------------
__global__ void combine_bias_kernel(const float* __restrict__ p0, const float* __restrict__ p1,
                                    const float* __restrict__ bias, float* __restrict__ dst) {
    size_t i = (size_t)blockIdx.x * blockDim.x + threadIdx.x;
    int col = ((int)(i & 31)) * 4;
    float4 a = ((const float4*)p0)[i], b = ((const float4*)p1)[i];
    ((float4*)dst)[i] = make_float4(a.x + b.x + bias[col], a.y + b.y + bias[col + 1],
                                    a.z + b.z + bias[col + 2], a.w + b.w + bias[col + 3]);
}

// ---------------- coefficient path (validated R1/R4) ----------------
__global__ void partial_kernel(const float* __restrict__ eigvs) {
    int b = blockIdx.x >> 5, chunk = blockIdx.x & 31, d = threadIdx.x;
    const float* p = eigvs + ((size_t)b * NN + (size_t)chunk * 128) * DD + d;
    float s = 0.f;
#pragma unroll 8
    for (int r = 0; r < 128; r++) s += p[(size_t)r * DD];
    g_partial[(b * 32 + chunk) * DD + d] = s;
}

__global__ void coeff_kernel(const float* __restrict__ Wa, const float* __restrict__ ba,
                             const float* __restrict__ Wb, const float* __restrict__ bb,
                             const float* __restrict__ Ws, const float* __restrict__ bs) {
    __shared__ float mean[DD];
    int b = blockIdx.x, d = threadIdx.x;
    float s = 0.f;
    for (int c = 0; c < 32; c++) s += g_partial[(b * 32 + c) * DD + d];
    mean[d] = s * (1.0f / NN);
    __syncthreads();
    if (d < RHO) {
        float a = 0.f, bv = 0.f, sv = 0.f;
        for (int e = 0; e < DD; e++) {
            float m = mean[e];
            a += m * Wa[e * RHO + d];
            bv += m * Wb[e * RHO + d];
            sv += m * Ws[e * NJ + d];
        }
        g_acoef[b * 8 + d] = a + ba[d];
        g_bcoef[b * 8 + d] = bv + bb[d];
        sv += bs[d];
        g_scale[b * 8 + d] = 5.0f / (1.0f + expf(-sv));
    }
}

__global__ void weight_kernel(const float* __restrict__ WS_, const float* __restrict__ WM,
                              const float* __restrict__ Ww, const float* __restrict__ bS,
                              const float* __restrict__ bM, const float* __restrict__ bw) {
    int blk = blockIdx.x, d = threadIdx.x;
    if (blk < 6 * DD) {
        int s = blk >> 7, i = blk & 127;
        const float* wsrc = (s == 0) ? (WS_ + i * DD) : (WM + (size_t)(s - 1) * DD * DD + i * DD);
        float acc = 0.f;
        for (int e = 0; e < DD; e++) acc += wsrc[e] * Ww[e * DD + d];
        bf16 h, l; split2(acc, h, l);
        g_Wc_hi[(size_t)blk * DD + d] = h;
        g_Wc_lo[(size_t)blk * DD + d] = l;
    } else {
        float acc = bw[d];
        for (int e = 0; e < DD; e++) {
            float cb = bS[e];
            for (int j = 0; j < NJ; j++) cb += bM[j * DD + e];
            acc += cb * Ww[e * DD + d];
        }
        g_cvec[d] = acc;
    }
}

// fbuild reads split-K partials directly (xt = p0 + p1), saving a combine pass
__global__ void fbuild_kernel(const float* __restrict__ eigvs) {
    int row0 = blockIdx.x * 16, d = threadIdx.x;
    for (int r = 0; r < 16; r++) {
        int row = row0 + r, b = row >> 12;
        const float* ac = g_acoef + b * 8;
        const float* bc = g_bcoef + b * 8;
        const float* sc = g_scale + b * 8;
        size_t idx = (size_t)row * DD + d;
        float e = eigvs[idx];
        float xv = g_p0[idx] + g_p1[idx];
        float To = 1.f, Te = e, h = bc[0];
#pragma unroll
        for (int i = 1; i < RHO; i++) {
            To = 2.f * e * Te - To;
            Te = 2.f * e * To - Te;
            h += bc[i] * To;
        }
        size_t fb = (size_t)row * (6 * DD);
        bf16 hh, hl; split2(h * xv, hh, hl);
        g_F_hi[fb + d] = hh; g_F_lo[fb + d] = hl;
#pragma unroll
        for (int j = 0; j < NJ; j++) {
            float sx = sc[j] * e;
            float To2 = 1.f, Te2 = sx, g = ac[0] * Te2;
#pragma unroll
            for (int i = 1; i < RHO; i++) {
                To2 = 2.f * sx * Te2 - To2;
                Te2 = 2.f * sx * To2 - Te2;
                g += ac[i] * Te2;
            }
            bf16 gh, gl; split2(g * xv, gh, gl);
            g_F_hi[fb + (1 + j) * DD + d] = gh;
            g_F_lo[fb + (1 + j) * DD + d] = gl;
        }
    }
}

// ---------------- mma.sync GEMM, BM=64 x BN=64, 128 threads, 2 smem stages ----------------
// Stage layout (32KB): A_hi[0,8K) A_lo[8K,16K) B_hi[16K,24K) B_lo[24K,32K)
// Register-level fragment double buffering across the 4 k16 sub-steps.
template <bool TRANSA>
__device__ __forceinline__ void loadA_async(u32 Abase, int k0, const bf16* Ah, const bf16* Al,
                                            int lda, int tid) {
#pragma unroll
    for (int half = 0; half < 2; half++) {
        const bf16* src = half ? Al : Ah;
        u32 ab = Abase + half * 8192;
#pragma unroll
        for (int i = 0; i < 4; i++) {
            int q = tid + i * 128;
            int row = q >> 3, ch = q & 7;
            const char* g;
            if (TRANSA) g = (const char*)(src + (size_t)(k0 + row) * lda) + ch * 16;
            else        g = (const char*)(src + (size_t)row * lda + k0) + ch * 16;
            u32 dst = ab + row * 128 + ((ch ^ (row & 7)) * 16);
            asm volatile("cp.async.cg.shared.global [%0], [%1], 16;" :: "r"(dst), "l"(g));
        }
    }
}

__device__ __forceinline__ void loadB_async(u32 Bbase, int k0, const bf16* Bh, const bf16* Bl,
                                            int ldb, int tid) {
#pragma unroll
    for (int half = 0; half < 2; half++) {
        const bf16* src = half ? Bl : Bh;
        u32 bb = Bbase + half * 8192;
#pragma unroll
        for (int i = 0; i < 4; i++) {
            int q = tid + i * 128;
            int kr = q >> 3, ch = q & 7;
            const char* g = (const char*)(src + (size_t)(k0 + kr) * ldb) + ch * 16;
            u32 dst = bb + kr * 128 + ((ch ^ (kr & 7)) * 16);
            asm volatile("cp.async.cg.shared.global [%0], [%1], 16;" :: "r"(dst), "l"(g));
        }
    }
}

template <bool TRANSA>
__device__ __forceinline__ void load_frags(u32 Ab, u32 Bb, int s, int lane, int wm, int wn,
                                           u32 ah[2][4], u32 al[2][4],
                                           u32 bh[2][4], u32 bl[2][4]) {
#pragma unroll
    for (int mt = 0; mt < 2; mt++) {
        u32 off;
        if (TRANSA) {
            int kr = 16 * s + (lane & 7) + ((lane >> 4) << 3);
            int mch = wm * 4 + mt * 2 + ((lane >> 3) & 1);
            off = kr * 128 + ((mch ^ (kr & 7)) << 4);
            ldsm4t(Ab + off, ah[mt]);
            ldsm4t(Ab + 8192 + off, al[mt]);
        } else {
            int row = wm * 32 + mt * 16 + (lane & 15);
            int ch = 2 * s + (lane >> 4);
            off = row * 128 + ((ch ^ (row & 7)) << 4);
            ldsm4(Ab + off, ah[mt]);
            ldsm4(Ab + 8192 + off, al[mt]);
        }
    }
#pragma unroll
    for (int nt = 0; nt < 2; nt++) {
        int kr = 16 * s + (lane & 7) + ((lane >> 3) & 1) * 8;
        int nch = wn * 4 + nt * 2 + (lane >> 4);
        u32 off = kr * 128 + ((nch ^ (kr & 7)) << 4);
        ldsm4t(Bb + off, bh[nt]);
        ldsm4t(Bb + 8192 + off, bl[nt]);
    }
}

// OUTMODE: 0 = fp32 partial (C0/C1 by ks), 2 = bf16 hi/lo split output
template <bool TRANSA, int OUTMODE>
__global__ void __launch_bounds__(128, 3)
mma_gemm(const bf16* __restrict__ Ah, const bf16* __restrict__ Al,
         const bf16* __restrict__ Bh, const bf16* __restrict__ Bl,
         float* __restrict__ C0, float* __restrict__ C1,
         bf16* __restrict__ Zh, bf16* __restrict__ Zl,
         int nsplit, int K, int lda, int ldb, size_t aB, size_t bB, size_t cB) {
    extern __shared__ char smem[];
    u32 sb = smem_u32(smem);
    int tid = threadIdx.x, lane = tid & 31, wid = tid >> 5;
    int wm = wid & 1, wn = wid >> 1;
    int bx = blockIdx.x, nh = blockIdx.y;
    int bz = blockIdx.z / nsplit, ks = blockIdx.z - bz * nsplit;
    const int Klocal = K / nsplit;
    const int kofs = ks * Klocal;

    Ah += bz * aB; Al += bz * aB;
    if (TRANSA) { Ah += (size_t)kofs * lda + (size_t)bx * 64; Al += (size_t)kofs * lda + (size_t)bx * 64; }
    else        { Ah += (size_t)bx * 64 * lda + kofs;         Al += (size_t)bx * 64 * lda + kofs; }
    Bh += bz * bB + (size_t)kofs * ldb + (size_t)nh * 64;
    Bl += bz * bB + (size_t)kofs * ldb + (size_t)nh * 64;

    float acc[2][4][4];
#pragma unroll
    for (int a = 0; a < 2; a++)
#pragma unroll
        for (int b = 0; b < 4; b++)
#pragma unroll
            for (int c = 0; c < 4; c++) acc[a][b][c] = 0.f;

    const int NCH = Klocal / KC;

#pragma unroll
    for (int s = 0; s < 2; s++) {
        u32 Abase = sb + s * STAGE_B;
        loadA_async<TRANSA>(Abase, s * KC, Ah, Al, lda, tid);
        loadB_async(Abase + 16384, s * KC, Bh, Bl, ldb, tid);
        asm volatile("cp.async.commit_group;" ::: "memory");
    }

    u32 ahb[2][2][4], alb[2][2][4], bhb[2][2][4], blb[2][2][4];

    for (int c = 0; c < NCH; c++) {
        int st = c & 1;
        if (c + 1 < NCH) asm volatile("cp.async.wait_group 1;" ::: "memory");
        else             asm volatile("cp.async.wait_group 0;" ::: "memory");
        __syncthreads();

        u32 Ab = sb + st * STAGE_B;
        u32 Bb = Ab + 16384;

        load_frags<TRANSA>(Ab, Bb, 0, lane, wm, wn, ahb[0], alb[0], bhb[0], blb[0]);
#pragma unroll
        for (int s = 0; s < 4; s++) {
            int cur = s & 1;
            if (s < 3)
                load_frags<TRANSA>(Ab, Bb, s + 1, lane, wm, wn,
                                   ahb[cur ^ 1], alb[cur ^ 1], bhb[cur ^ 1], blb[cur ^ 1]);
#pragma unroll
            for (int mt = 0; mt < 2; mt++)
#pragma unroll
                for (int nt = 0; nt < 2; nt++)
#pragma unroll
                    for (int oc = 0; oc < 2; oc++) {
                        float* cc = acc[mt][nt * 2 + oc];
                        mma16816(cc, ahb[cur][mt], &bhb[cur][nt][oc * 2]);
                        mma16816(cc, ahb[cur][mt], &blb[cur][nt][oc * 2]);
                        mma16816(cc, alb[cur][mt], &bhb[cur][nt][oc * 2]);
                    }
        }
        __syncthreads();
        if (c + 2 < NCH) {
            u32 Abase = sb + st * STAGE_B;
            loadA_async<TRANSA>(Abase, (c + 2) * KC, Ah, Al, lda, tid);
            loadB_async(Abase + 16384, (c + 2) * KC, Bh, Bl, ldb, tid);
            asm volatile("cp.async.commit_group;" ::: "memory");
        }
    }

    // epilogue
    float* C = (ks == 0) ? C0 : C1;
#pragma unroll
    for (int mt = 0; mt < 2; mt++)
#pragma unroll
        for (int j = 0; j < 4; j++) {
            int mloc = bx * 64 + wm * 32 + mt * 16 + (lane >> 2);
            int col = nh * 64 + wn * 32 + j * 8 + (lane & 3) * 2;
#pragma unroll
            for (int rr = 0; rr < 2; rr++) {
                float v0 = acc[mt][j][rr * 2], v1 = acc[mt][j][rr * 2 + 1];
                size_t off = (size_t)(mloc + rr * 8) * 128 + col;
                if (OUTMODE == 2) {
                    bf16 h0, l0, h1, l1;
                    split2(v0, h0, l0); split2(v1, h1, l1);
                    *(u32*)(Zh + bz * cB + off) = packb(h0, h1);
                    *(u32*)(Zl + bz * cB + off) = packb(l0, l1);
                } else {
                    *(float2*)(C + bz * cB + off) = make_float2(v0, v1);
                }
            }
        }
}

// ---------------------------------------------------------------
extern "C" void kernel_launch(void* const* d_in, const int* in_sizes, int n_in,
                              void* d_out, int out_size) {
    const float* eigvs = (const float*)d_in[0];
    const float* x = (const float*)d_in[1];
    const float* U = (const float*)d_in[2];
    const float* Wa = (const float*)d_in[3];
    const float* ba = (const float*)d_in[4];
    const float* Wb = (const float*)d_in[5];
    const float* bb = (const float*)d_in[6];
    const float* Ws = (const float*)d_in[7];
    const float* bs = (const float*)d_in[8];
    const float* WS_ = (const float*)d_in[9];
    const float* bS = (const float*)d_in[10];
    const float* WM = (const float*)d_in[11];
    const float* bM = (const float*)d_in[12];
    const float* Ww = (const float*)d_in[13];
    const float* bw = (const float*)d_in[14];
    float* out = (float*)d_out;

    cudaFuncSetAttribute(mma_gemm<true, 0>, cudaFuncAttributeMaxDynamicSharedMemorySize, SMEM_TOTAL);
    cudaFuncSetAttribute(mma_gemm<false, 2>, cudaFuncAttributeMaxDynamicSharedMemorySize, SMEM_TOTAL);
    cudaFuncSetAttribute(mma_gemm<false, 0>, cudaFuncAttributeMaxDynamicSharedMemorySize, SMEM_TOTAL);

    bf16 *pUh, *pUl, *pxh, *pxl, *pZh, *pZl, *pFh, *pFl, *pWh, *pWl;
    float *pcv, *pp0, *pp1;
    cudaGetSymbolAddress((void**)&pUh, g_U_hi);
    cudaGetSymbolAddress((void**)&pUl, g_U_lo);
    cudaGetSymbolAddress((void**)&pxh, g_x_hi);
    cudaGetSymbolAddress((void**)&pxl, g_x_lo);
    cudaGetSymbolAddress((void**)&pZh, g_Z_hi);
    cudaGetSymbolAddress((void**)&pZl, g_Z_lo);
    cudaGetSymbolAddress((void**)&pFh, g_F_hi);
    cudaGetSymbolAddress((void**)&pFl, g_F_lo);
    cudaGetSymbolAddress((void**)&pWh, g_Wc_hi);
    cudaGetSymbolAddress((void**)&pWl, g_Wc_lo);
    cudaGetSymbolAddress((void**)&pcv, g_cvec);
    cudaGetSymbolAddress((void**)&pp0, g_p0);
    cudaGetSymbolAddress((void**)&pp1, g_p1);

    const size_t sU = (size_t)NN * NN;
    const size_t sX = (size_t)NN * DD;

    convert_split_kernel<<<32768, 256>>>(U, pUh, pUl);
    convert_split_kernel<<<1024, 256>>>(x, pxh, pxl);
    partial_kernel<<<64, 128>>>(eigvs);

    // xt = U^T x : split-K=2 partials (combined inside fbuild)
    mma_gemm<true, 0><<<dim3(64, 2, 4), 128, SMEM_TOTAL>>>(
        pUh, pUl, pxh, pxl, pp0, pp1, nullptr, nullptr,
        2, NN, NN, DD, sU, sX, sX);

    weight_kernel<<<769, 128>>>(WS_, WM, Ww, bS, bM, bw);
    coeff_kernel<<<2, 128>>>(Wa, ba, Wb, bb, Ws, bs);
    fbuild_kernel<<<512, 128>>>(eigvs);

    // Z = F @ Wc : flat M=8192, K=768; unsplit; output split bf16
    mma_gemm<false, 2><<<dim3(128, 2, 1), 128, SMEM_TOTAL>>>(
        pFh, pFl, pWh, pWl, nullptr, nullptr, pZh, pZl,
        1, 6 * DD, 6 * DD, DD, 0, 0, 0);

    // out = U @ Z + cvec : split-K=2, partials then combine with bias
    mma_gemm<false, 0><<<dim3(64, 2, 4), 128, SMEM_TOTAL>>>(
        pUh, pUl, pZh, pZl, pp0, pp1, nullptr, nullptr,
        2, NN, NN, DD, sU, sX, sX);
    combine_bias_kernel<<<1024, 256>>>(pp0, pp1, pcv, out);
}

// round 9
// speedup vs baseline: 1.0181x; 1.0092x over previous
#include <cuda_runtime.h>
#include <cuda_bf16.h>
#include <cstdint>
#include <cstddef>

typedef __nv_bfloat16 bf16;
typedef unsigned int u32;

#define NN 4096
#define DD 128
#define NB 2
#define RHO 5
#define NJ 5
#define KC 64
// Stage (48KB): A_hi[0,16K) A_lo[16K,32K) B_hi[32K,40K) B_lo[40K,48K)
#define STAGE_B 49152
#define SMEM_TOTAL (2 * STAGE_B)

// ---------------- device scratch ----------------
__device__ bf16 g_U_hi[(size_t)NB * NN * NN];
__device__ bf16 g_U_lo[(size_t)NB * NN * NN];
__device__ bf16 g_x_hi[(size_t)NB * NN * DD];
__device__ bf16 g_x_lo[(size_t)NB * NN * DD];
__device__ bf16 g_Z_hi[(size_t)NB * NN * DD];
__device__ bf16 g_Z_lo[(size_t)NB * NN * DD];
__device__ float g_p0[(size_t)NB * NN * DD];
__device__ float g_p1[(size_t)NB * NN * DD];
__device__ bf16 g_F_hi[(size_t)NB * NN * 6 * DD];
__device__ bf16 g_F_lo[(size_t)NB * NN * 6 * DD];
__device__ bf16 g_Wc_hi[6 * DD * DD];   // [768 k][128 d]
__device__ bf16 g_Wc_lo[6 * DD * DD];
__device__ float g_partial[NB * 32 * DD];
__device__ float g_acoef[NB * 8];
__device__ float g_bcoef[NB * 8];
__device__ float g_scale[NB * 8];
__device__ float g_cvec[DD];

// ---------------- helpers ----------------
__device__ __forceinline__ u32 smem_u32(const void* p) {
    u32 a;
    asm("{ .reg .u64 t; cvta.to.shared.u64 t, %1; cvt.u32.u64 %0, t; }" : "=r"(a) : "l"(p));
    return a;
}
__device__ __forceinline__ void split2(float v, bf16& h, bf16& l) {
    h = __float2bfloat16_rn(v);
    l = __float2bfloat16_rn(v - __bfloat162float(h));
}
__device__ __forceinline__ u32 packb(bf16 a, bf16 b) {
    return (u32)__bfloat16_as_ushort(a) | ((u32)__bfloat16_as_ushort(b) << 16);
}
__device__ __forceinline__ void ldsm4(u32 a, u32* r) {
    asm volatile("ldmatrix.sync.aligned.m8n8.x4.shared.b16 {%0,%1,%2,%3}, [%4];"
                 : "=r"(r[0]), "=r"(r[1]), "=r"(r[2]), "=r"(r[3]) : "r"(a));
}
__device__ __forceinline__ void ldsm4t(u32 a, u32* r) {
    asm volatile("ldmatrix.sync.aligned.m8n8.x4.trans.shared.b16 {%0,%1,%2,%3}, [%4];"
                 : "=r"(r[0]), "=r"(r[1]), "=r"(r[2]), "=r"(r[3]) : "r"(a));
}
__device__ __forceinline__ void mma16816(float* c, const u32* a, const u32* b) {
    asm volatile(
        "mma.sync.aligned.m16n8k16.row.col.f32.bf16.bf16.f32 "
        "{%0,%1,%2,%3}, {%4,%5,%6,%7}, {%8,%9}, {%0,%1,%2,%3};"
        : "+f"(c[0]), "+f"(c[1]), "+f"(c[2]), "+f"(c[3])
        : "r"(a[0]), "r"(a[1]), "r"(a[2]), "r"(a[3]), "r"(b[0]), "r"(b[1]));
}

// ---------------- elementwise fp32 -> bf16 hi/lo ----------------
__global__ void convert_split_kernel(const float* __restrict__ src, bf16* __restrict__ oh,
                                     bf16* __restrict__ ol) {
    size_t idx = (size_t)blockIdx.x * blockDim.x + threadIdx.x;
    float4 v = ((const float4*)src)[idx];
    bf16 h0, l0, h1, l1, h2, l2, h3, l3;
    split2(v.x, h0, l0); split2(v.y, h1, l1);
    split2(v.z, h2, l2); split2(v.w, h3, l3);
    ((u32*)oh)[idx * 2] = packb(h0, h1);
    ((u32*)oh)[idx * 2 + 1] = packb(h2, h3);
    ((u32*)ol)[idx * 2] = packb(l0, l1);
    ((u32*)ol)[idx * 2 + 1] = packb(l2, l3);
}

// ---------------- split-K bias combine (deterministic) ----------------
__global__ void combine_bias_kernel(const float* __restrict__ p0, const float* __restrict__ p1,
                                    const float* __restrict__ bias, float* __restrict__ dst) {
    size_t i = (size_t)blockIdx.x * blockDim.x + threadIdx.x;
    int col = ((int)(i & 31)) * 4;
    float4 a = ((const float4*)p0)[i], b = ((const float4*)p1)[i];
    ((float4*)dst)[i] = make_float4(a.x + b.x + bias[col], a.y + b.y + bias[col + 1],
                                    a.z + b.z + bias[col + 2], a.w + b.w + bias[col + 3]);
}

// ---------------- coefficient path (validated) ----------------
__global__ void partial_kernel(const float* __restrict__ eigvs) {
    int b = blockIdx.x >> 5, chunk = blockIdx.x & 31, d = threadIdx.x;
    const float* p = eigvs + ((size_t)b * NN + (size_t)chunk * 128) * DD + d;
    float s = 0.f;
#pragma unroll 8
    for (int r = 0; r < 128; r++) s += p[(size_t)r * DD];
    g_partial[(b * 32 + chunk) * DD + d] = s;
}

__global__ void coeff_kernel(const float* __restrict__ Wa, const float* __restrict__ ba,
                             const float* __restrict__ Wb, const float* __restrict__ bb,
                             const float* __restrict__ Ws, const float* __restrict__ bs) {
    __shared__ float mean[DD];
    int b = blockIdx.x, d = threadIdx.x;
    float s = 0.f;
    for (int c = 0; c < 32; c++) s += g_partial[(b * 32 + c) * DD + d];
    mean[d] = s * (1.0f / NN);
    __syncthreads();
    if (d < RHO) {
        float a = 0.f, bv = 0.f, sv = 0.f;
        for (int e = 0; e < DD; e++) {
            float m = mean[e];
            a += m * Wa[e * RHO + d];
            bv += m * Wb[e * RHO + d];
            sv += m * Ws[e * NJ + d];
        }
        g_acoef[b * 8 + d] = a + ba[d];
        g_bcoef[b * 8 + d] = bv + bb[d];
        sv += bs[d];
        g_scale[b * 8 + d] = 5.0f / (1.0f + expf(-sv));
    }
}

__global__ void weight_kernel(const float* __restrict__ WS_, const float* __restrict__ WM,
                              const float* __restrict__ Ww, const float* __restrict__ bS,
                              const float* __restrict__ bM, const float* __restrict__ bw) {
    int blk = blockIdx.x, d = threadIdx.x;
    if (blk < 6 * DD) {
        int s = blk >> 7, i = blk & 127;
        const float* wsrc = (s == 0) ? (WS_ + i * DD) : (WM + (size_t)(s - 1) * DD * DD + i * DD);
        float acc = 0.f;
        for (int e = 0; e < DD; e++) acc += wsrc[e] * Ww[e * DD + d];
        bf16 h, l; split2(acc, h, l);
        g_Wc_hi[(size_t)blk * DD + d] = h;
        g_Wc_lo[(size_t)blk * DD + d] = l;
    } else {
        float acc = bw[d];
        for (int e = 0; e < DD; e++) {
            float cb = bS[e];
            for (int j = 0; j < NJ; j++) cb += bM[j * DD + e];
            acc += cb * Ww[e * DD + d];
        }
        g_cvec[d] = acc;
    }
}

// fbuild reads split-K partials directly (xt = p0 + p1)
__global__ void fbuild_kernel(const float* __restrict__ eigvs) {
    int row0 = blockIdx.x * 16, d = threadIdx.x;
    for (int r = 0; r < 16; r++) {
        int row = row0 + r, b = row >> 12;
        const float* ac = g_acoef + b * 8;
        const float* bc = g_bcoef + b * 8;
        const float* sc = g_scale + b * 8;
        size_t idx = (size_t)row * DD + d;
        float e = eigvs[idx];
        float xv = g_p0[idx] + g_p1[idx];
        float To = 1.f, Te = e, h = bc[0];
#pragma unroll
        for (int i = 1; i < RHO; i++) {
            To = 2.f * e * Te - To;
            Te = 2.f * e * To - Te;
            h += bc[i] * To;
        }
        size_t fb = (size_t)row * (6 * DD);
        bf16 hh, hl; split2(h * xv, hh, hl);
        g_F_hi[fb + d] = hh; g_F_lo[fb + d] = hl;
#pragma unroll
        for (int j = 0; j < NJ; j++) {
            float sx = sc[j] * e;
            float To2 = 1.f, Te2 = sx, g = ac[0] * Te2;
#pragma unroll
            for (int i = 1; i < RHO; i++) {
                To2 = 2.f * sx * Te2 - To2;
                Te2 = 2.f * sx * To2 - Te2;
                g += ac[i] * Te2;
            }
            bf16 gh, gl; split2(g * xv, gh, gl);
            g_F_hi[fb + (1 + j) * DD + d] = gh;
            g_F_lo[fb + (1 + j) * DD + d] = gl;
        }
    }
}

// ---------------- mma.sync GEMM, BM=128 x BN=64, 128 threads, 2 smem stages ----------------
// 4 warps, warp tile 64x32 (wm: 64-row half, wn: 32-col half).
// TRANSA: A[k][m] rows=KC, 256B/row. else A[m][k] rows=128, 128B/row.
template <bool TRANSA>
__device__ __forceinline__ void loadA_async(u32 Abase, int k0, const bf16* Ah, const bf16* Al,
                                            int lda, int tid) {
#pragma unroll
    for (int half = 0; half < 2; half++) {
        const bf16* src = half ? Al : Ah;
        u32 ab = Abase + half * 16384;
#pragma unroll
        for (int i = 0; i < 8; i++) {
            int q = tid + i * 128;
            u32 dst; const char* g;
            if (TRANSA) {
                int row = q >> 4, ch = q & 15;   // 64 k-rows x 16 chunks (256B)
                g = (const char*)(src + (size_t)(k0 + row) * lda) + ch * 16;
                dst = ab + row * 256 + ((ch ^ (row & 7)) * 16);
            } else {
                int row = q >> 3, ch = q & 7;    // 128 m-rows x 8 chunks (128B)
                g = (const char*)(src + (size_t)row * lda + k0) + ch * 16;
                dst = ab + row * 128 + ((ch ^ (row & 7)) * 16);
            }
            asm volatile("cp.async.cg.shared.global [%0], [%1], 16;" :: "r"(dst), "l"(g));
        }
    }
}

__device__ __forceinline__ void loadB_async(u32 Bbase, int k0, const bf16* Bh, const bf16* Bl,
                                            int ldb, int tid) {
#pragma unroll
    for (int half = 0; half < 2; half++) {
        const bf16* src = half ? Bl : Bh;
        u32 bb = Bbase + half * 8192;
#pragma unroll
        for (int i = 0; i < 4; i++) {
            int q = tid + i * 128;
            int kr = q >> 3, ch = q & 7;
            const char* g = (const char*)(src + (size_t)(k0 + kr) * ldb) + ch * 16;
            u32 dst = bb + kr * 128 + ((ch ^ (kr & 7)) * 16);
            asm volatile("cp.async.cg.shared.global [%0], [%1], 16;" :: "r"(dst), "l"(g));
        }
    }
}

// OUTMODE: 0 = fp32 partial (C0/C1 by ks), 2 = bf16 hi/lo split output
template <bool TRANSA, int OUTMODE>
__global__ void __launch_bounds__(128, 2)
mma_gemm(const bf16* __restrict__ Ah, const bf16* __restrict__ Al,
         const bf16* __restrict__ Bh, const bf16* __restrict__ Bl,
         float* __restrict__ C0, float* __restrict__ C1,
         bf16* __restrict__ Zh, bf16* __restrict__ Zl,
         int nsplit, int K, int lda, int ldb, size_t aB, size_t bB, size_t cB) {
    extern __shared__ char smem[];
    u32 sb = smem_u32(smem);
    int tid = threadIdx.x, lane = tid & 31, wid = tid >> 5;
    int wm = wid & 1, wn = wid >> 1;
    int bx = blockIdx.x, nh = blockIdx.y;
    int bz = blockIdx.z / nsplit, ks = blockIdx.z - bz * nsplit;
    const int Klocal = K / nsplit;
    const int kofs = ks * Klocal;

    Ah += bz * aB; Al += bz * aB;
    if (TRANSA) { Ah += (size_t)kofs * lda + (size_t)bx * 128; Al += (size_t)kofs * lda + (size_t)bx * 128; }
    else        { Ah += (size_t)bx * 128 * lda + kofs;         Al += (size_t)bx * 128 * lda + kofs; }
    Bh += bz * bB + (size_t)kofs * ldb + (size_t)nh * 64;
    Bl += bz * bB + (size_t)kofs * ldb + (size_t)nh * 64;

    float acc[4][4][4];
#pragma unroll
    for (int a = 0; a < 4; a++)
#pragma unroll
        for (int b = 0; b < 4; b++)
#pragma unroll
            for (int c = 0; c < 4; c++) acc[a][b][c] = 0.f;

    const int NCH = Klocal / KC;

#pragma unroll
    for (int s = 0; s < 2; s++) {
        u32 Abase = sb + s * STAGE_B;
        loadA_async<TRANSA>(Abase, s * KC, Ah, Al, lda, tid);
        loadB_async(Abase + 32768, s * KC, Bh, Bl, ldb, tid);
        asm volatile("cp.async.commit_group;" ::: "memory");
    }

    for (int c = 0; c < NCH; c++) {
        int st = c & 1;
        if (c + 1 < NCH) asm volatile("cp.async.wait_group 1;" ::: "memory");
        else             asm volatile("cp.async.wait_group 0;" ::: "memory");
        __syncthreads();

        u32 Ab = sb + st * STAGE_B;
        u32 Bb = Ab + 32768;
#pragma unroll
        for (int s = 0; s < 4; s++) {
            u32 ah[4][4], al[4][4], bh[2][4], bl[2][4];
#pragma unroll
            for (int mt = 0; mt < 4; mt++) {
                u32 off;
                if (TRANSA) {
                    int kr = 16 * s + (lane & 7) + ((lane >> 4) << 3);
                    int mch = wm * 8 + mt * 2 + ((lane >> 3) & 1);
                    off = kr * 256 + ((mch ^ (kr & 7)) << 4);
                    ldsm4t(Ab + off, ah[mt]);
                    ldsm4t(Ab + 16384 + off, al[mt]);
                } else {
                    int row = wm * 64 + mt * 16 + (lane & 15);
                    int ch = 2 * s + (lane >> 4);
                    off = row * 128 + ((ch ^ (row & 7)) << 4);
                    ldsm4(Ab + off, ah[mt]);
                    ldsm4(Ab + 16384 + off, al[mt]);
                }
            }
#pragma unroll
            for (int nt = 0; nt < 2; nt++) {
                int kr = 16 * s + (lane & 7) + ((lane >> 3) & 1) * 8;
                int nch = wn * 4 + nt * 2 + (lane >> 4);
                u32 off = kr * 128 + ((nch ^ (kr & 7)) << 4);
                ldsm4t(Bb + off, bh[nt]);
                ldsm4t(Bb + 8192 + off, bl[nt]);
            }
#pragma unroll
            for (int mt = 0; mt < 4; mt++)
#pragma unroll
                for (int nt = 0; nt < 2; nt++)
#pragma unroll
                    for (int oc = 0; oc < 2; oc++) {
                        float* cc = acc[mt][nt * 2 + oc];
                        mma16816(cc, ah[mt], &bh[nt][oc * 2]);
                        mma16816(cc, ah[mt], &bl[nt][oc * 2]);
                        mma16816(cc, al[mt], &bh[nt][oc * 2]);
                    }
        }
        __syncthreads();
        if (c + 2 < NCH) {
            u32 Abase = sb + st * STAGE_B;
            loadA_async<TRANSA>(Abase, (c + 2) * KC, Ah, Al, lda, tid);
            loadB_async(Abase + 32768, (c + 2) * KC, Bh, Bl, ldb, tid);
            asm volatile("cp.async.commit_group;" ::: "memory");
        }
    }

    // epilogue
    float* C = (ks == 0) ? C0 : C1;
#pragma unroll
    for (int mt = 0; mt < 4; mt++)
#pragma unroll
        for (int j = 0; j < 4; j++) {
            int mloc = bx * 128 + wm * 64 + mt * 16 + (lane >> 2);
            int col = nh * 64 + wn * 32 + j * 8 + (lane & 3) * 2;
#pragma unroll
            for (int rr = 0; rr < 2; rr++) {
                float v0 = acc[mt][j][rr * 2], v1 = acc[mt][j][rr * 2 + 1];
                size_t off = (size_t)(mloc + rr * 8) * 128 + col;
                if (OUTMODE == 2) {
                    bf16 h0, l0, h1, l1;
                    split2(v0, h0, l0); split2(v1, h1, l1);
                    *(u32*)(Zh + bz * cB + off) = packb(h0, h1);
                    *(u32*)(Zl + bz * cB + off) = packb(l0, l1);
                } else {
                    *(float2*)(C + bz * cB + off) = make_float2(v0, v1);
                }
            }
        }
}

// ---------------------------------------------------------------
extern "C" void kernel_launch(void* const* d_in, const int* in_sizes, int n_in,
                              void* d_out, int out_size) {
    const float* eigvs = (const float*)d_in[0];
    const float* x = (const float*)d_in[1];
    const float* U = (const float*)d_in[2];
    const float* Wa = (const float*)d_in[3];
    const float* ba = (const float*)d_in[4];
    const float* Wb = (const float*)d_in[5];
    const float* bb = (const float*)d_in[6];
    const float* Ws = (const float*)d_in[7];
    const float* bs = (const float*)d_in[8];
    const float* WS_ = (const float*)d_in[9];
    const float* bS = (const float*)d_in[10];
    const float* WM = (const float*)d_in[11];
    const float* bM = (const float*)d_in[12];
    const float* Ww = (const float*)d_in[13];
    const float* bw = (const float*)d_in[14];
    float* out = (float*)d_out;

    cudaFuncSetAttribute(mma_gemm<true, 0>, cudaFuncAttributeMaxDynamicSharedMemorySize, SMEM_TOTAL);
    cudaFuncSetAttribute(mma_gemm<false, 2>, cudaFuncAttributeMaxDynamicSharedMemorySize, SMEM_TOTAL);
    cudaFuncSetAttribute(mma_gemm<false, 0>, cudaFuncAttributeMaxDynamicSharedMemorySize, SMEM_TOTAL);

    bf16 *pUh, *pUl, *pxh, *pxl, *pZh, *pZl, *pFh, *pFl, *pWh, *pWl;
    float *pcv, *pp0, *pp1;
    cudaGetSymbolAddress((void**)&pUh, g_U_hi);
    cudaGetSymbolAddress((void**)&pUl, g_U_lo);
    cudaGetSymbolAddress((void**)&pxh, g_x_hi);
    cudaGetSymbolAddress((void**)&pxl, g_x_lo);
    cudaGetSymbolAddress((void**)&pZh, g_Z_hi);
    cudaGetSymbolAddress((void**)&pZl, g_Z_lo);
    cudaGetSymbolAddress((void**)&pFh, g_F_hi);
    cudaGetSymbolAddress((void**)&pFl, g_F_lo);
    cudaGetSymbolAddress((void**)&pWh, g_Wc_hi);
    cudaGetSymbolAddress((void**)&pWl, g_Wc_lo);
    cudaGetSymbolAddress((void**)&pcv, g_cvec);
    cudaGetSymbolAddress((void**)&pp0, g_p0);
    cudaGetSymbolAddress((void**)&pp1, g_p1);

    const size_t sU = (size_t)NN * NN;
    const size_t sX = (size_t)NN * DD;

    convert_split_kernel<<<32768, 256>>>(U, pUh, pUl);
    convert_split_kernel<<<1024, 256>>>(x, pxh, pxl);
    partial_kernel<<<64, 128>>>(eigvs);

    // xt = U^T x : split-K=2 partials (combined inside fbuild)
    mma_gemm<true, 0><<<dim3(32, 2, 4), 128, SMEM_TOTAL>>>(
        pUh, pUl, pxh, pxl, pp0, pp1, nullptr, nullptr,
        2, NN, NN, DD, sU, sX, sX);

    weight_kernel<<<769, 128>>>(WS_, WM, Ww, bS, bM, bw);
    coeff_kernel<<<2, 128>>>(Wa, ba, Wb, bb, Ws, bs);
    fbuild_kernel<<<512, 128>>>(eigvs);

    // Z = F @ Wc : flat M=8192, K=768; unsplit; output split bf16
    mma_gemm<false, 2><<<dim3(64, 2, 1), 128, SMEM_TOTAL>>>(
        pFh, pFl, pWh, pWl, nullptr, nullptr, pZh, pZl,
        1, 6 * DD, 6 * DD, DD, 0, 0, 0);

    // out = U @ Z + cvec : split-K=2, partials then combine with bias
    mma_gemm<false, 0><<<dim3(32, 2, 4), 128, SMEM_TOTAL>>>(
        pUh, pUl, pZh, pZl, pp0, pp1, nullptr, nullptr,
        2, NN, NN, DD, sU, sX, sX);
    combine_bias_kernel<<<1024, 256>>>(pp0, pp1, pcv, out);
}